// round 4
// baseline (speedup 1.0000x reference)
#include <cuda_runtime.h>
#include <cuda_bf16.h>
#include <math.h>

// ---------------------------------------------------------------------------
// GNNRegressor: 2x GCNConv(+relu) -> global_mean_pool -> Linear+relu -> Linear+sigmoid
// N=50000 nodes, E=1.6M edges, IN=384, HID=128, G=512, OUT=5
// Strategy: per-call CSR build (by dst), register-accumulating aggregate
// (1 warp/node), 128x128 SIMT fp32 GEMM.
// ---------------------------------------------------------------------------

#define N_NODES 50000
#define N_GRAPHS 512
#define HID 128
#define IN_DIM 384
#define E_MAX 1600000

// Scratch (device globals; no allocation allowed)
__device__ float g_H[(size_t)N_NODES * HID];     // gemm output (pre-aggregate)
__device__ float g_B[(size_t)N_NODES * HID];     // aggregate output (post-relu)
__device__ float g_dis[N_NODES];                 // rsqrt(deg+1)
__device__ int   g_deg[N_NODES];
__device__ int   g_row[N_NODES + 1];
__device__ int   g_cursor[N_NODES];
__device__ int   g_csr[E_MAX];
__device__ int   g_partials[256];
__device__ float g_pool[(size_t)N_GRAPHS * HID];
__device__ float g_cnt[N_GRAPHS];

__device__ __forceinline__ void red_add_v4(float* addr, float4 v) {
    asm volatile("red.global.add.v4.f32 [%0], {%1,%2,%3,%4};"
                 :: "l"(addr), "f"(v.x), "f"(v.y), "f"(v.z), "f"(v.w)
                 : "memory");
}

// ---- degree + CSR build -----------------------------------------------------
__global__ void k_zero_deg(int n) {
    int i = blockIdx.x * blockDim.x + threadIdx.x;
    if (i < n) g_deg[i] = 0;
}

__global__ void k_edge_count(const int* __restrict__ dst, int E) {
    int e = blockIdx.x * blockDim.x + threadIdx.x;
    if (e < E) atomicAdd(&g_deg[dst[e]], 1);
}

__global__ void k_dis(int n) {
    int i = blockIdx.x * blockDim.x + threadIdx.x;
    if (i < n) g_dis[i] = rsqrtf((float)(g_deg[i] + 1));
}

// block sums over 256-elem chunks of deg (covers n+1 with deg[n]=0 virtual)
__global__ void k_block_sums(int n) {
    __shared__ int sh[256];
    int i = blockIdx.x * 256 + threadIdx.x;
    int v = (i < n) ? g_deg[i] : 0;
    sh[threadIdx.x] = v;
    __syncthreads();
    #pragma unroll
    for (int off = 128; off > 0; off >>= 1) {
        if (threadIdx.x < off) sh[threadIdx.x] += sh[threadIdx.x + off];
        __syncthreads();
    }
    if (threadIdx.x == 0) g_partials[blockIdx.x] = sh[0];
}

// exclusive scan of partials (<=256) in one block
__global__ void k_scan_partials(int nb) {
    __shared__ int sh[256];
    int t = threadIdx.x;
    int v = (t < nb) ? g_partials[t] : 0;
    sh[t] = v;
    __syncthreads();
    #pragma unroll
    for (int off = 1; off < 256; off <<= 1) {
        int x = (t >= off) ? sh[t - off] : 0;
        __syncthreads();
        sh[t] += x;
        __syncthreads();
    }
    if (t < nb) g_partials[t] = sh[t] - v;  // exclusive
}

// final scan: row_start[i] = exclusive prefix of deg; also copy to cursor
__global__ void k_scan_final(int n) {
    __shared__ int sh[256];
    int i = blockIdx.x * 256 + threadIdx.x;
    int t = threadIdx.x;
    int v = (i < n) ? g_deg[i] : 0;
    sh[t] = v;
    __syncthreads();
    #pragma unroll
    for (int off = 1; off < 256; off <<= 1) {
        int x = (t >= off) ? sh[t - off] : 0;
        __syncthreads();
        sh[t] += x;
        __syncthreads();
    }
    int excl = sh[t] - v + g_partials[blockIdx.x];
    if (i <= n) {
        g_row[i] = excl;
        if (i < n) g_cursor[i] = excl;
    }
}

__global__ void k_fill_csr(const int* __restrict__ src, const int* __restrict__ dst, int E) {
    int e = blockIdx.x * blockDim.x + threadIdx.x;
    if (e < E) {
        int d = dst[e];
        int pos = atomicAdd(&g_cursor[d], 1);
        g_csr[pos] = src[e];
    }
}

// ---- GEMM: C[M,128] = A[M,K] @ W[K,128], fp32 SIMT, 128x128 tile -----------
template <int KTOT>
__global__ __launch_bounds__(256, 2)
void k_gemm(const float* __restrict__ A, const float* __restrict__ W,
            float* __restrict__ C, int M) {
    constexpr int BM = 128, BN = 128, BK = 8;
    __shared__ float As[BK][BM];
    __shared__ float Bs[BK][BN];
    const int t = threadIdx.x;                 // 256 threads
    const int rg = t >> 4;                     // 0..15
    const int cg = t & 15;                     // 0..15
    const int row0 = blockIdx.x * BM;

    const int arow = t >> 1;                   // 0..127
    const int acol = (t & 1) * 4;              // 0 or 4
    const int brow = t >> 5;                   // 0..7
    const int bcol = (t & 31) * 4;             // 0..124

    float acc00[4][4] = {}, acc01[4][4] = {}, acc10[4][4] = {}, acc11[4][4] = {};

    for (int k0 = 0; k0 < KTOT; k0 += BK) {
        int grow = row0 + arow;
        float4 av = (grow < M) ? *(const float4*)&A[(size_t)grow * KTOT + k0 + acol]
                               : make_float4(0.f, 0.f, 0.f, 0.f);
        As[acol + 0][arow] = av.x;
        As[acol + 1][arow] = av.y;
        As[acol + 2][arow] = av.z;
        As[acol + 3][arow] = av.w;
        *(float4*)&Bs[brow][bcol] = *(const float4*)&W[(size_t)(k0 + brow) * BN + bcol];
        __syncthreads();

        #pragma unroll
        for (int kk = 0; kk < BK; kk++) {
            float4 a0 = *(float4*)&As[kk][rg * 4];
            float4 a1 = *(float4*)&As[kk][rg * 4 + 64];
            float4 b0 = *(float4*)&Bs[kk][cg * 4];
            float4 b1 = *(float4*)&Bs[kk][cg * 4 + 64];
            float a0v[4] = {a0.x, a0.y, a0.z, a0.w};
            float a1v[4] = {a1.x, a1.y, a1.z, a1.w};
            float b0v[4] = {b0.x, b0.y, b0.z, b0.w};
            float b1v[4] = {b1.x, b1.y, b1.z, b1.w};
            #pragma unroll
            for (int i = 0; i < 4; i++)
                #pragma unroll
                for (int j = 0; j < 4; j++) {
                    acc00[i][j] += a0v[i] * b0v[j];
                    acc01[i][j] += a0v[i] * b1v[j];
                    acc10[i][j] += a1v[i] * b0v[j];
                    acc11[i][j] += a1v[i] * b1v[j];
                }
        }
        __syncthreads();
    }

    #pragma unroll
    for (int i = 0; i < 4; i++) {
        int r0 = row0 + rg * 4 + i;
        int r1 = r0 + 64;
        if (r0 < M) {
            *(float4*)&C[(size_t)r0 * 128 + cg * 4]      = *(float4*)&acc00[i][0];
            *(float4*)&C[(size_t)r0 * 128 + cg * 4 + 64] = *(float4*)&acc01[i][0];
        }
        if (r1 < M) {
            *(float4*)&C[(size_t)r1 * 128 + cg * 4]      = *(float4*)&acc10[i][0];
            *(float4*)&C[(size_t)r1 * 128 + cg * 4 + 64] = *(float4*)&acc11[i][0];
        }
    }
}

// ---- aggregate: out[d] = relu(dis_d*(Sum_{s in row d} dis_s*h[s] + dis_d*h[d]) + bias)
__global__ void k_aggregate(const float* __restrict__ H, const float* __restrict__ bias,
                            float* __restrict__ out, int n) {
    int warp = (blockIdx.x * blockDim.x + threadIdx.x) >> 5;
    int lane = threadIdx.x & 31;
    if (warp >= n) return;
    const int node = warp;
    const float4* __restrict__ H4 = (const float4*)H;

    int beg = g_row[node];
    int end = g_row[node + 1];

    float4 a0 = {0, 0, 0, 0}, a1 = {0, 0, 0, 0}, a2 = {0, 0, 0, 0}, a3 = {0, 0, 0, 0};

    int j = beg;
    for (; j + 3 < end; j += 4) {
        int s0 = __ldg(&g_csr[j + 0]);
        int s1 = __ldg(&g_csr[j + 1]);
        int s2 = __ldg(&g_csr[j + 2]);
        int s3 = __ldg(&g_csr[j + 3]);
        float w0 = __ldg(&g_dis[s0]);
        float w1 = __ldg(&g_dis[s1]);
        float w2 = __ldg(&g_dis[s2]);
        float w3 = __ldg(&g_dis[s3]);
        float4 h0 = __ldg(&H4[(size_t)s0 * 32 + lane]);
        float4 h1 = __ldg(&H4[(size_t)s1 * 32 + lane]);
        float4 h2 = __ldg(&H4[(size_t)s2 * 32 + lane]);
        float4 h3 = __ldg(&H4[(size_t)s3 * 32 + lane]);
        a0.x += w0 * h0.x; a0.y += w0 * h0.y; a0.z += w0 * h0.z; a0.w += w0 * h0.w;
        a1.x += w1 * h1.x; a1.y += w1 * h1.y; a1.z += w1 * h1.z; a1.w += w1 * h1.w;
        a2.x += w2 * h2.x; a2.y += w2 * h2.y; a2.z += w2 * h2.z; a2.w += w2 * h2.w;
        a3.x += w3 * h3.x; a3.y += w3 * h3.y; a3.z += w3 * h3.z; a3.w += w3 * h3.w;
    }
    for (; j < end; j++) {
        int s = __ldg(&g_csr[j]);
        float w = __ldg(&g_dis[s]);
        float4 h = __ldg(&H4[(size_t)s * 32 + lane]);
        a0.x += w * h.x; a0.y += w * h.y; a0.z += w * h.z; a0.w += w * h.w;
    }

    float dd = g_dis[node];
    float4 hs = __ldg(&H4[(size_t)node * 32 + lane]);
    float4 acc;
    acc.x = dd * ((a0.x + a1.x) + (a2.x + a3.x) + dd * hs.x);
    acc.y = dd * ((a0.y + a1.y) + (a2.y + a3.y) + dd * hs.y);
    acc.z = dd * ((a0.z + a1.z) + (a2.z + a3.z) + dd * hs.z);
    acc.w = dd * ((a0.w + a1.w) + (a2.w + a3.w) + dd * hs.w);

    float4 b = *(const float4*)&bias[lane * 4];
    acc.x = fmaxf(acc.x + b.x, 0.f);
    acc.y = fmaxf(acc.y + b.y, 0.f);
    acc.z = fmaxf(acc.z + b.z, 0.f);
    acc.w = fmaxf(acc.w + b.w, 0.f);
    ((float4*)out)[(size_t)node * 32 + lane] = acc;
}

// ---- pooling ---------------------------------------------------------------
__global__ void k_pool_zero() {
    int i = blockIdx.x * blockDim.x + threadIdx.x;
    if (i < N_GRAPHS * HID) g_pool[i] = 0.0f;
    if (i < N_GRAPHS) g_cnt[i] = 0.0f;
}

__global__ void k_pool(const float* __restrict__ H, const int* __restrict__ batch, int n) {
    int idx = blockIdx.x * blockDim.x + threadIdx.x;
    int node = idx >> 5, chunk = idx & 31;
    if (node >= n) return;
    int b = __ldg(&batch[node]);
    float4 h = ((const float4*)(H + (size_t)node * 128))[chunk];
    red_add_v4(&g_pool[(size_t)b * 128 + chunk * 4], h);
    if (chunk == 0) atomicAdd(&g_cnt[b], 1.0f);
}

// ---- MLP head: [512,128] -> relu(@Wl1[128,64]+bl1) -> sigmoid(@Wl2[64,5]+bl2)
__global__ void k_mlp(const float* __restrict__ Wl1, const float* __restrict__ bl1,
                      const float* __restrict__ Wl2, const float* __restrict__ bl2,
                      float* __restrict__ out) {
    __shared__ float gm[128];
    __shared__ float hid[64];
    int gi = blockIdx.x;
    int t = threadIdx.x;  // 64 threads
    float inv = 1.0f / fmaxf(g_cnt[gi], 1.0f);
    gm[t]      = g_pool[(size_t)gi * 128 + t] * inv;
    gm[t + 64] = g_pool[(size_t)gi * 128 + t + 64] * inv;
    __syncthreads();
    float s = bl1[t];
    #pragma unroll 8
    for (int k = 0; k < 128; k++) s += gm[k] * Wl1[k * 64 + t];
    hid[t] = fmaxf(s, 0.0f);
    __syncthreads();
    if (t < 5) {
        float o = bl2[t];
        #pragma unroll
        for (int k = 0; k < 64; k++) o += hid[k] * Wl2[k * 5 + t];
        out[gi * 5 + t] = 1.0f / (1.0f + expf(-o));
    }
}

// ---------------------------------------------------------------------------
extern "C" void kernel_launch(void* const* d_in, const int* in_sizes, int n_in,
                              void* d_out, int out_size) {
    const float* x    = (const float*)d_in[0];
    const int*   ei   = (const int*)d_in[1];   // [2, E] int32
    const int*   batch= (const int*)d_in[2];
    const float* W1   = (const float*)d_in[3];
    const float* b1   = (const float*)d_in[4];
    const float* W2   = (const float*)d_in[5];
    const float* b2   = (const float*)d_in[6];
    const float* Wl1  = (const float*)d_in[7];
    const float* bl1  = (const float*)d_in[8];
    const float* Wl2  = (const float*)d_in[9];
    const float* bl2  = (const float*)d_in[10];
    float* out = (float*)d_out;

    const int N = in_sizes[2];          // 50000
    const int E = in_sizes[1] / 2;      // 1600000
    const int* src = ei;
    const int* dst = ei + E;

    float* H = nullptr; float* B = nullptr;
    cudaGetSymbolAddress((void**)&H, g_H);
    cudaGetSymbolAddress((void**)&B, g_B);

    const int T = 256;
    const int nb_scan = (N + 1 + 255) / 256;   // scan covers indices 0..N

    // CSR build + dis
    k_zero_deg<<<(N + T - 1) / T, T>>>(N);
    k_edge_count<<<(E + T - 1) / T, T>>>(dst, E);
    k_dis<<<(N + T - 1) / T, T>>>(N);
    k_block_sums<<<nb_scan, 256>>>(N);
    k_scan_partials<<<1, 256>>>(nb_scan);
    k_scan_final<<<nb_scan, 256>>>(N);
    k_fill_csr<<<(E + T - 1) / T, T>>>(src, dst, E);

    // layer 1: gemm(x,W1) -> H ; aggregate(H) -> B (relu'd)
    k_gemm<IN_DIM><<<(N + 127) / 128, 256>>>(x, W1, H, N);
    k_aggregate<<<(N * 32 + T - 1) / T, T>>>(H, b1, B, N);

    // layer 2: gemm(B,W2) -> H ; aggregate(H) -> B
    k_gemm<HID><<<(N + 127) / 128, 256>>>(B, W2, H, N);
    k_aggregate<<<(N * 32 + T - 1) / T, T>>>(H, b2, B, N);

    // pooling + head
    k_pool_zero<<<(N_GRAPHS * HID + T - 1) / T, T>>>();
    k_pool<<<(N * 32 + T - 1) / T, T>>>(B, batch, N);
    k_mlp<<<N_GRAPHS, 64>>>(Wl1, bl1, Wl2, bl2, out);
}

// round 5
// speedup vs baseline: 1.1764x; 1.1764x over previous
#include <cuda_runtime.h>
#include <cuda_fp16.h>
#include <math.h>

// ---------------------------------------------------------------------------
// GNNRegressor: 2x GCNConv(+relu) -> global_mean_pool -> Linear+relu -> Linear+sigmoid
// N=50000 nodes, E=1.6M edges, IN=384, HID=128, G=512, OUT=5
// Strategy: CSR by dst; GEMM writes dis-prescaled fp16 rows; aggregate sums
// fp16 rows in fp32 (halved L2 gather traffic); layer-2 aggregate fuses pooling.
// ---------------------------------------------------------------------------

#define N_NODES 50000
#define N_GRAPHS 512
#define HID 128
#define IN_DIM 384
#define E_MAX 1600000

// Scratch (device globals; no allocation allowed)
__device__ __half g_H16[(size_t)N_NODES * HID];  // gemm output, dis-prescaled fp16
__device__ float  g_B[(size_t)N_NODES * HID];    // layer-1 aggregate output (fp32)
__device__ float  g_dis[N_NODES];                // rsqrt(deg+1)
__device__ int    g_deg[N_NODES];
__device__ int    g_row[N_NODES + 1];
__device__ int    g_cursor[N_NODES];
__device__ int    g_csr[E_MAX];
__device__ int    g_partials[256];
__device__ float  g_pool[(size_t)N_GRAPHS * HID];
__device__ float  g_cnt[N_GRAPHS];

__device__ __forceinline__ void red_add_v4(float* addr, float4 v) {
    asm volatile("red.global.add.v4.f32 [%0], {%1,%2,%3,%4};"
                 :: "l"(addr), "f"(v.x), "f"(v.y), "f"(v.z), "f"(v.w)
                 : "memory");
}

// ---- degree + CSR build -----------------------------------------------------
__global__ void k_zero_deg(int n) {
    int i = blockIdx.x * blockDim.x + threadIdx.x;
    if (i < n) g_deg[i] = 0;
}

__global__ void k_edge_count(const int* __restrict__ dst, int E) {
    int e = blockIdx.x * blockDim.x + threadIdx.x;
    if (e < E) atomicAdd(&g_deg[dst[e]], 1);
}

__global__ void k_block_sums(int n) {
    __shared__ int sh[256];
    int i = blockIdx.x * 256 + threadIdx.x;
    int v = (i < n) ? g_deg[i] : 0;
    sh[threadIdx.x] = v;
    __syncthreads();
    #pragma unroll
    for (int off = 128; off > 0; off >>= 1) {
        if (threadIdx.x < off) sh[threadIdx.x] += sh[threadIdx.x + off];
        __syncthreads();
    }
    if (threadIdx.x == 0) g_partials[blockIdx.x] = sh[0];
}

__global__ void k_scan_partials(int nb) {
    __shared__ int sh[256];
    int t = threadIdx.x;
    int v = (t < nb) ? g_partials[t] : 0;
    sh[t] = v;
    __syncthreads();
    #pragma unroll
    for (int off = 1; off < 256; off <<= 1) {
        int x = (t >= off) ? sh[t - off] : 0;
        __syncthreads();
        sh[t] += x;
        __syncthreads();
    }
    if (t < nb) g_partials[t] = sh[t] - v;  // exclusive
}

// final scan: row offsets + cursor copy + dis = rsqrt(deg+1)
__global__ void k_scan_final(int n) {
    __shared__ int sh[256];
    int i = blockIdx.x * 256 + threadIdx.x;
    int t = threadIdx.x;
    int v = (i < n) ? g_deg[i] : 0;
    sh[t] = v;
    __syncthreads();
    #pragma unroll
    for (int off = 1; off < 256; off <<= 1) {
        int x = (t >= off) ? sh[t - off] : 0;
        __syncthreads();
        sh[t] += x;
        __syncthreads();
    }
    int excl = sh[t] - v + g_partials[blockIdx.x];
    if (i <= n) {
        g_row[i] = excl;
        if (i < n) {
            g_cursor[i] = excl;
            g_dis[i] = rsqrtf((float)(v + 1));
        }
    }
}

__global__ void k_fill_csr(const int* __restrict__ src, const int* __restrict__ dst, int E) {
    int e = blockIdx.x * blockDim.x + threadIdx.x;
    if (e < E) {
        int d = dst[e];
        int pos = atomicAdd(&g_cursor[d], 1);
        g_csr[pos] = src[e];
    }
}

// ---- GEMM: C16[row] = half( dis[row] * (A[row,:] @ W) ), 128x128 tile -------
template <int KTOT>
__global__ __launch_bounds__(256, 2)
void k_gemm_h(const float* __restrict__ A, const float* __restrict__ W,
              __half* __restrict__ C16, int M) {
    constexpr int BM = 128, BN = 128, BK = 8;
    __shared__ float As[BK][BM];
    __shared__ float Bs[BK][BN];
    const int t = threadIdx.x;                 // 256 threads
    const int rg = t >> 4;                     // 0..15
    const int cg = t & 15;                     // 0..15
    const int row0 = blockIdx.x * BM;

    const int arow = t >> 1;                   // 0..127
    const int acol = (t & 1) * 4;              // 0 or 4
    const int brow = t >> 5;                   // 0..7
    const int bcol = (t & 31) * 4;             // 0..124

    float acc00[4][4] = {}, acc01[4][4] = {}, acc10[4][4] = {}, acc11[4][4] = {};

    for (int k0 = 0; k0 < KTOT; k0 += BK) {
        int grow = row0 + arow;
        float4 av = (grow < M) ? *(const float4*)&A[(size_t)grow * KTOT + k0 + acol]
                               : make_float4(0.f, 0.f, 0.f, 0.f);
        As[acol + 0][arow] = av.x;
        As[acol + 1][arow] = av.y;
        As[acol + 2][arow] = av.z;
        As[acol + 3][arow] = av.w;
        *(float4*)&Bs[brow][bcol] = *(const float4*)&W[(size_t)(k0 + brow) * BN + bcol];
        __syncthreads();

        #pragma unroll
        for (int kk = 0; kk < BK; kk++) {
            float4 a0 = *(float4*)&As[kk][rg * 4];
            float4 a1 = *(float4*)&As[kk][rg * 4 + 64];
            float4 b0 = *(float4*)&Bs[kk][cg * 4];
            float4 b1 = *(float4*)&Bs[kk][cg * 4 + 64];
            float a0v[4] = {a0.x, a0.y, a0.z, a0.w};
            float a1v[4] = {a1.x, a1.y, a1.z, a1.w};
            float b0v[4] = {b0.x, b0.y, b0.z, b0.w};
            float b1v[4] = {b1.x, b1.y, b1.z, b1.w};
            #pragma unroll
            for (int i = 0; i < 4; i++)
                #pragma unroll
                for (int j = 0; j < 4; j++) {
                    acc00[i][j] += a0v[i] * b0v[j];
                    acc01[i][j] += a0v[i] * b1v[j];
                    acc10[i][j] += a1v[i] * b0v[j];
                    acc11[i][j] += a1v[i] * b1v[j];
                }
        }
        __syncthreads();
    }

    #pragma unroll
    for (int i = 0; i < 4; i++) {
        int r0 = row0 + rg * 4 + i;
        int r1 = r0 + 64;
        if (r0 < M) {
            float d0 = g_dis[r0];
            __half2 h0 = __floats2half2_rn(d0 * acc00[i][0], d0 * acc00[i][1]);
            __half2 h1 = __floats2half2_rn(d0 * acc00[i][2], d0 * acc00[i][3]);
            __half2 h2 = __floats2half2_rn(d0 * acc01[i][0], d0 * acc01[i][1]);
            __half2 h3 = __floats2half2_rn(d0 * acc01[i][2], d0 * acc01[i][3]);
            *(__half2*)&C16[(size_t)r0 * 128 + cg * 4]          = h0;
            *(__half2*)&C16[(size_t)r0 * 128 + cg * 4 + 2]      = h1;
            *(__half2*)&C16[(size_t)r0 * 128 + cg * 4 + 64]     = h2;
            *(__half2*)&C16[(size_t)r0 * 128 + cg * 4 + 64 + 2] = h3;
        }
        if (r1 < M) {
            float d1 = g_dis[r1];
            __half2 h0 = __floats2half2_rn(d1 * acc10[i][0], d1 * acc10[i][1]);
            __half2 h1 = __floats2half2_rn(d1 * acc10[i][2], d1 * acc10[i][3]);
            __half2 h2 = __floats2half2_rn(d1 * acc11[i][0], d1 * acc11[i][1]);
            __half2 h3 = __floats2half2_rn(d1 * acc11[i][2], d1 * acc11[i][3]);
            *(__half2*)&C16[(size_t)r1 * 128 + cg * 4]          = h0;
            *(__half2*)&C16[(size_t)r1 * 128 + cg * 4 + 2]      = h1;
            *(__half2*)&C16[(size_t)r1 * 128 + cg * 4 + 64]     = h2;
            *(__half2*)&C16[(size_t)r1 * 128 + cg * 4 + 64 + 2] = h3;
        }
    }
}

// ---- shared aggregate core ---------------------------------------------------
// Rows in H16 are already dis[s]-scaled. Per node d:
//   acc = Sum_{s in nbrs} H16[s] + H16[d]          (self-loop, same scaling)
//   out = relu(dis[d] * acc + bias)
__device__ __forceinline__ float4 agg_core(const __half* __restrict__ H16,
                                           const float* __restrict__ bias,
                                           int node, int lane) {
    const uint2* __restrict__ H2 = (const uint2*)H16;  // 4 halves per lane
    int beg = g_row[node];
    int end = g_row[node + 1];

    float a0x = 0, a0y = 0, a0z = 0, a0w = 0;
    float a1x = 0, a1y = 0, a1z = 0, a1w = 0;

    int j = beg;
    for (; j + 1 < end; j += 2) {
        int s0 = __ldg(&g_csr[j]);
        int s1 = __ldg(&g_csr[j + 1]);
        uint2 r0 = __ldg(&H2[(size_t)s0 * 32 + lane]);
        uint2 r1 = __ldg(&H2[(size_t)s1 * 32 + lane]);
        float2 f00 = __half22float2(*(__half2*)&r0.x);
        float2 f01 = __half22float2(*(__half2*)&r0.y);
        float2 f10 = __half22float2(*(__half2*)&r1.x);
        float2 f11 = __half22float2(*(__half2*)&r1.y);
        a0x += f00.x; a0y += f00.y; a0z += f01.x; a0w += f01.y;
        a1x += f10.x; a1y += f10.y; a1z += f11.x; a1w += f11.y;
    }
    if (j < end) {
        int s = __ldg(&g_csr[j]);
        uint2 r = __ldg(&H2[(size_t)s * 32 + lane]);
        float2 f0 = __half22float2(*(__half2*)&r.x);
        float2 f1 = __half22float2(*(__half2*)&r.y);
        a0x += f0.x; a0y += f0.y; a0z += f1.x; a0w += f1.y;
    }

    // self-loop: node's own pre-scaled row
    {
        uint2 r = __ldg(&H2[(size_t)node * 32 + lane]);
        float2 f0 = __half22float2(*(__half2*)&r.x);
        float2 f1 = __half22float2(*(__half2*)&r.y);
        a0x += f0.x; a0y += f0.y; a0z += f1.x; a0w += f1.y;
    }

    float dd = g_dis[node];
    float4 b = *(const float4*)&bias[lane * 4];
    float4 o;
    o.x = fmaxf(dd * (a0x + a1x) + b.x, 0.f);
    o.y = fmaxf(dd * (a0y + a1y) + b.y, 0.f);
    o.z = fmaxf(dd * (a0z + a1z) + b.z, 0.f);
    o.w = fmaxf(dd * (a0w + a1w) + b.w, 0.f);
    return o;
}

// layer-1 aggregate: write fp32 rows (input to gemm2)
__global__ void k_agg_f32(const __half* __restrict__ H16, const float* __restrict__ bias,
                          float* __restrict__ out, int n) {
    int warp = (blockIdx.x * blockDim.x + threadIdx.x) >> 5;
    int lane = threadIdx.x & 31;
    if (warp >= n) return;
    float4 o = agg_core(H16, bias, warp, lane);
    ((float4*)out)[(size_t)warp * 32 + lane] = o;
}

// layer-2 aggregate fused with mean-pool accumulation (RED into g_pool)
__global__ void k_agg_pool(const __half* __restrict__ H16, const float* __restrict__ bias,
                           const int* __restrict__ batch, int n) {
    int warp = (blockIdx.x * blockDim.x + threadIdx.x) >> 5;
    int lane = threadIdx.x & 31;
    if (warp >= n) return;
    float4 o = agg_core(H16, bias, warp, lane);
    int b = __ldg(&batch[warp]);
    red_add_v4(&g_pool[(size_t)b * 128 + lane * 4], o);
}

// ---- pooling setup -----------------------------------------------------------
__global__ void k_pool_zero() {
    int i = blockIdx.x * blockDim.x + threadIdx.x;
    if (i < N_GRAPHS * HID) g_pool[i] = 0.0f;
    if (i < N_GRAPHS) g_cnt[i] = 0.0f;
}

__global__ void k_cnt(const int* __restrict__ batch, int n) {
    int i = blockIdx.x * blockDim.x + threadIdx.x;
    if (i < n) atomicAdd(&g_cnt[batch[i]], 1.0f);
}

// ---- MLP head ------------------------------------------------------------------
__global__ void k_mlp(const float* __restrict__ Wl1, const float* __restrict__ bl1,
                      const float* __restrict__ Wl2, const float* __restrict__ bl2,
                      float* __restrict__ out) {
    __shared__ float gm[128];
    __shared__ float hid[64];
    int gi = blockIdx.x;
    int t = threadIdx.x;  // 64 threads
    float inv = 1.0f / fmaxf(g_cnt[gi], 1.0f);
    gm[t]      = g_pool[(size_t)gi * 128 + t] * inv;
    gm[t + 64] = g_pool[(size_t)gi * 128 + t + 64] * inv;
    __syncthreads();
    float s = bl1[t];
    #pragma unroll 8
    for (int k = 0; k < 128; k++) s += gm[k] * Wl1[k * 64 + t];
    hid[t] = fmaxf(s, 0.0f);
    __syncthreads();
    if (t < 5) {
        float o = bl2[t];
        #pragma unroll
        for (int k = 0; k < 64; k++) o += hid[k] * Wl2[k * 5 + t];
        out[gi * 5 + t] = 1.0f / (1.0f + expf(-o));
    }
}

// ---------------------------------------------------------------------------
extern "C" void kernel_launch(void* const* d_in, const int* in_sizes, int n_in,
                              void* d_out, int out_size) {
    const float* x    = (const float*)d_in[0];
    const int*   ei   = (const int*)d_in[1];   // [2, E] int32
    const int*   batch= (const int*)d_in[2];
    const float* W1   = (const float*)d_in[3];
    const float* b1   = (const float*)d_in[4];
    const float* W2   = (const float*)d_in[5];
    const float* b2   = (const float*)d_in[6];
    const float* Wl1  = (const float*)d_in[7];
    const float* bl1  = (const float*)d_in[8];
    const float* Wl2  = (const float*)d_in[9];
    const float* bl2  = (const float*)d_in[10];
    float* out = (float*)d_out;

    const int N = in_sizes[2];          // 50000
    const int E = in_sizes[1] / 2;      // 1600000
    const int* src = ei;
    const int* dst = ei + E;

    __half* H16 = nullptr; float* B = nullptr;
    cudaGetSymbolAddress((void**)&H16, g_H16);
    cudaGetSymbolAddress((void**)&B, g_B);

    const int T = 256;
    const int nb_scan = (N + 1 + 255) / 256;

    // CSR build + dis
    k_zero_deg<<<(N + T - 1) / T, T>>>(N);
    k_edge_count<<<(E + T - 1) / T, T>>>(dst, E);
    k_block_sums<<<nb_scan, 256>>>(N);
    k_scan_partials<<<1, 256>>>(nb_scan);
    k_scan_final<<<nb_scan, 256>>>(N);
    k_fill_csr<<<(E + T - 1) / T, T>>>(src, dst, E);

    // layer 1: gemm(x,W1) -> H16 (dis-scaled fp16) ; aggregate -> B (fp32)
    k_gemm_h<IN_DIM><<<(N + 127) / 128, 256>>>(x, W1, H16, N);
    k_agg_f32<<<(N * 32 + T - 1) / T, T>>>(H16, b1, B, N);

    // layer 2: gemm(B,W2) -> H16 ; aggregate fused with pooling
    k_gemm_h<HID><<<(N + 127) / 128, 256>>>(B, W2, H16, N);
    k_pool_zero<<<(N_GRAPHS * HID + T - 1) / T, T>>>();
    k_cnt<<<(N + T - 1) / T, T>>>(batch, N);
    k_agg_pool<<<(N * 32 + T - 1) / T, T>>>(H16, b2, batch, N);

    // head
    k_mlp<<<N_GRAPHS, 64>>>(Wl1, bl1, Wl2, bl2, out);
}

// round 7
// speedup vs baseline: 1.7663x; 1.5015x over previous
#include <cuda_runtime.h>
#include <cuda_fp16.h>
#include <cstdint>
#include <math.h>

typedef unsigned int u32;

// ---------------------------------------------------------------------------
// GNNRegressor: 2x GCNConv(+relu) -> global_mean_pool -> Linear+relu -> Linear+sigmoid
// N=50000 nodes, E=1.6M edges, IN=384, HID=128, G=512, OUT=5
// Strategy: CSR by dst; tensor-core fp16 MMA GEMMs (fp32 accum, on-the-fly
// fp32->fp16 staging); GEMM writes dis-prescaled fp16 rows; aggregates sum
// fp16 rows in fp32; layer-2 aggregate fuses mean-pool RED.
// ---------------------------------------------------------------------------

#define N_NODES 50000
#define N_GRAPHS 512
#define HID 128
#define IN_DIM 384
#define E_MAX 1600000

__device__ __half g_H16[(size_t)N_NODES * HID];
__device__ float  g_B[(size_t)N_NODES * HID];
__device__ float  g_dis[N_NODES];
__device__ int    g_deg[N_NODES];
__device__ int    g_row[N_NODES + 1];
__device__ int    g_cursor[N_NODES];
__device__ int    g_csr[E_MAX];
__device__ int    g_partials[256];
__device__ float  g_pool[(size_t)N_GRAPHS * HID];
__device__ float  g_cnt[N_GRAPHS];

__device__ __forceinline__ void red_add_v4(float* addr, float4 v) {
    asm volatile("red.global.add.v4.f32 [%0], {%1,%2,%3,%4};"
                 :: "l"(addr), "f"(v.x), "f"(v.y), "f"(v.z), "f"(v.w)
                 : "memory");
}

__device__ __forceinline__ void ldsm_x4(u32& r0, u32& r1, u32& r2, u32& r3, u32 addr) {
    asm volatile("ldmatrix.sync.aligned.m8n8.x4.shared.b16 {%0,%1,%2,%3}, [%4];"
                 : "=r"(r0), "=r"(r1), "=r"(r2), "=r"(r3) : "r"(addr));
}

__device__ __forceinline__ void ldsm_x4_t(u32& r0, u32& r1, u32& r2, u32& r3, u32 addr) {
    asm volatile("ldmatrix.sync.aligned.m8n8.x4.trans.shared.b16 {%0,%1,%2,%3}, [%4];"
                 : "=r"(r0), "=r"(r1), "=r"(r2), "=r"(r3) : "r"(addr));
}

__device__ __forceinline__ void mma16816(float& c0, float& c1, float& c2, float& c3,
                                         u32 a0, u32 a1, u32 a2, u32 a3,
                                         u32 b0, u32 b1) {
    asm volatile("mma.sync.aligned.m16n8k16.row.col.f32.f16.f16.f32 "
                 "{%0,%1,%2,%3}, {%4,%5,%6,%7}, {%8,%9}, {%0,%1,%2,%3};"
                 : "+f"(c0), "+f"(c1), "+f"(c2), "+f"(c3)
                 : "r"(a0), "r"(a1), "r"(a2), "r"(a3), "r"(b0), "r"(b1));
}

__device__ __forceinline__ u32 smem_addr(const void* p) {
    return (u32)__cvta_generic_to_shared(p);
}

// ---- degree + CSR build -----------------------------------------------------
__global__ void k_zero_deg(int n) {
    int i = blockIdx.x * blockDim.x + threadIdx.x;
    if (i < n) g_deg[i] = 0;
}

__global__ void k_edge_count(const int* __restrict__ dst, int E) {
    int e = blockIdx.x * blockDim.x + threadIdx.x;
    if (e < E) atomicAdd(&g_deg[dst[e]], 1);
}

__global__ void k_block_sums(int n) {
    __shared__ int sh[256];
    int i = blockIdx.x * 256 + threadIdx.x;
    int v = (i < n) ? g_deg[i] : 0;
    sh[threadIdx.x] = v;
    __syncthreads();
    #pragma unroll
    for (int off = 128; off > 0; off >>= 1) {
        if (threadIdx.x < off) sh[threadIdx.x] += sh[threadIdx.x + off];
        __syncthreads();
    }
    if (threadIdx.x == 0) g_partials[blockIdx.x] = sh[0];
}

__global__ void k_scan_partials(int nb) {
    __shared__ int sh[256];
    int t = threadIdx.x;
    int v = (t < nb) ? g_partials[t] : 0;
    sh[t] = v;
    __syncthreads();
    #pragma unroll
    for (int off = 1; off < 256; off <<= 1) {
        int x = (t >= off) ? sh[t - off] : 0;
        __syncthreads();
        sh[t] += x;
        __syncthreads();
    }
    if (t < nb) g_partials[t] = sh[t] - v;
}

__global__ void k_scan_final(int n) {
    __shared__ int sh[256];
    int i = blockIdx.x * 256 + threadIdx.x;
    int t = threadIdx.x;
    int v = (i < n) ? g_deg[i] : 0;
    sh[t] = v;
    __syncthreads();
    #pragma unroll
    for (int off = 1; off < 256; off <<= 1) {
        int x = (t >= off) ? sh[t - off] : 0;
        __syncthreads();
        sh[t] += x;
        __syncthreads();
    }
    int excl = sh[t] - v + g_partials[blockIdx.x];
    if (i <= n) {
        g_row[i] = excl;
        if (i < n) {
            g_cursor[i] = excl;
            g_dis[i] = rsqrtf((float)(v + 1));
        }
    }
}

__global__ void k_fill_csr(const int* __restrict__ src, const int* __restrict__ dst, int E) {
    int e = blockIdx.x * blockDim.x + threadIdx.x;
    if (e < E) {
        int d = dst[e];
        int pos = atomicAdd(&g_cursor[d], 1);
        g_csr[pos] = src[e];
    }
}

// ---- tensor-core GEMM: C16[row] = half( dis[row] * (A[row,:] @ W) ) ---------
template <int KTOT>
__global__ __launch_bounds__(256, 2)
void k_gemm_mma(const float* __restrict__ A, const float* __restrict__ W,
                __half* __restrict__ C16, int M) {
    const int BM = 128, BN = 128, BK = 32;
    const int AP = 40;    // As row pitch (halves)
    const int BP = 136;   // Bs row pitch (halves)
    __shared__ __half As[128 * 40];
    __shared__ __half Bs[32 * 136];

    const int t = threadIdx.x;
    const int lane = t & 31;
    const int warp = t >> 5;
    const int wm = warp & 3;        // 32-row strip
    const int wn = warp >> 2;       // 64-col strip
    const int row0 = blockIdx.x * BM;
    const int lr = lane & 15;
    const int lc = lane >> 4;

    float c[2][8][4];
    #pragma unroll
    for (int i = 0; i < 2; i++)
        #pragma unroll
        for (int j = 0; j < 8; j++)
            #pragma unroll
            for (int k = 0; k < 4; k++) c[i][j][k] = 0.f;

    for (int k0 = 0; k0 < KTOT; k0 += BK) {
        // stage A tile: 128 rows x 32 fp32 -> fp16
        #pragma unroll
        for (int i = 0; i < 4; i++) {
            int idx = t * 4 + i;
            int r = idx >> 3;
            int seg = idx & 7;
            int gr = row0 + r;
            float4 v = (gr < M) ? *(const float4*)&A[(size_t)gr * KTOT + k0 + seg * 4]
                                : make_float4(0.f, 0.f, 0.f, 0.f);
            __half2 h0 = __floats2half2_rn(v.x, v.y);
            __half2 h1 = __floats2half2_rn(v.z, v.w);
            *(__half2*)&As[r * AP + seg * 4]     = h0;
            *(__half2*)&As[r * AP + seg * 4 + 2] = h1;
        }
        // stage W tile: 32 rows x 128 fp32 -> fp16
        #pragma unroll
        for (int i = 0; i < 4; i++) {
            int idx = t * 4 + i;
            int r = idx >> 5;
            int seg = idx & 31;
            float4 v = *(const float4*)&W[(size_t)(k0 + r) * BN + seg * 4];
            __half2 h0 = __floats2half2_rn(v.x, v.y);
            __half2 h1 = __floats2half2_rn(v.z, v.w);
            *(__half2*)&Bs[r * BP + seg * 4]     = h0;
            *(__half2*)&Bs[r * BP + seg * 4 + 2] = h1;
        }
        __syncthreads();

        #pragma unroll
        for (int ki = 0; ki < 2; ki++) {
            u32 a0[4];
            u32 a1[4];
            {
                u32 ad0 = smem_addr(&As[(wm * 32 + lr) * AP + ki * 16 + lc * 8]);
                ldsm_x4(a0[0], a0[1], a0[2], a0[3], ad0);
                u32 ad1 = smem_addr(&As[(wm * 32 + 16 + lr) * AP + ki * 16 + lc * 8]);
                ldsm_x4(a1[0], a1[1], a1[2], a1[3], ad1);
            }
            u32 b[4][4];
            #pragma unroll
            for (int np = 0; np < 4; np++) {
                u32 ad = smem_addr(&Bs[(ki * 16 + lr) * BP + wn * 64 + np * 16 + lc * 8]);
                ldsm_x4_t(b[np][0], b[np][1], b[np][2], b[np][3], ad);
            }
            #pragma unroll
            for (int np = 0; np < 4; np++) {
                mma16816(c[0][np * 2][0], c[0][np * 2][1], c[0][np * 2][2], c[0][np * 2][3],
                         a0[0], a0[1], a0[2], a0[3], b[np][0], b[np][1]);
                mma16816(c[0][np * 2 + 1][0], c[0][np * 2 + 1][1], c[0][np * 2 + 1][2], c[0][np * 2 + 1][3],
                         a0[0], a0[1], a0[2], a0[3], b[np][2], b[np][3]);
                mma16816(c[1][np * 2][0], c[1][np * 2][1], c[1][np * 2][2], c[1][np * 2][3],
                         a1[0], a1[1], a1[2], a1[3], b[np][0], b[np][1]);
                mma16816(c[1][np * 2 + 1][0], c[1][np * 2 + 1][1], c[1][np * 2 + 1][2], c[1][np * 2 + 1][3],
                         a1[0], a1[1], a1[2], a1[3], b[np][2], b[np][3]);
            }
        }
        __syncthreads();
    }

    // epilogue: prescale by dis[row], convert fp16, store
    #pragma unroll
    for (int mi = 0; mi < 2; mi++) {
        int r_lo = row0 + wm * 32 + mi * 16 + (lane >> 2);
        int r_hi = r_lo + 8;
        float d_lo = (r_lo < M) ? g_dis[r_lo] : 0.f;
        float d_hi = (r_hi < M) ? g_dis[r_hi] : 0.f;
        #pragma unroll
        for (int ni = 0; ni < 8; ni++) {
            int col = wn * 64 + ni * 8 + (lane & 3) * 2;
            if (r_lo < M) {
                __half2 h = __floats2half2_rn(d_lo * c[mi][ni][0], d_lo * c[mi][ni][1]);
                *(__half2*)&C16[(size_t)r_lo * 128 + col] = h;
            }
            if (r_hi < M) {
                __half2 h = __floats2half2_rn(d_hi * c[mi][ni][2], d_hi * c[mi][ni][3]);
                *(__half2*)&C16[(size_t)r_hi * 128 + col] = h;
            }
        }
    }
}

// ---- aggregate core ----------------------------------------------------------
__device__ __forceinline__ float4 agg_core(const __half* __restrict__ H16,
                                           const float* __restrict__ bias,
                                           int node, int lane) {
    const uint2* __restrict__ H2 = (const uint2*)H16;
    int beg = g_row[node];
    int end = g_row[node + 1];

    float a0x = 0, a0y = 0, a0z = 0, a0w = 0;
    float a1x = 0, a1y = 0, a1z = 0, a1w = 0;

    int j = beg;
    for (; j + 1 < end; j += 2) {
        int s0 = __ldg(&g_csr[j]);
        int s1 = __ldg(&g_csr[j + 1]);
        uint2 r0 = __ldg(&H2[(size_t)s0 * 32 + lane]);
        uint2 r1 = __ldg(&H2[(size_t)s1 * 32 + lane]);
        float2 f00 = __half22float2(*(__half2*)&r0.x);
        float2 f01 = __half22float2(*(__half2*)&r0.y);
        float2 f10 = __half22float2(*(__half2*)&r1.x);
        float2 f11 = __half22float2(*(__half2*)&r1.y);
        a0x += f00.x; a0y += f00.y; a0z += f01.x; a0w += f01.y;
        a1x += f10.x; a1y += f10.y; a1z += f11.x; a1w += f11.y;
    }
    if (j < end) {
        int s = __ldg(&g_csr[j]);
        uint2 r = __ldg(&H2[(size_t)s * 32 + lane]);
        float2 f0 = __half22float2(*(__half2*)&r.x);
        float2 f1 = __half22float2(*(__half2*)&r.y);
        a0x += f0.x; a0y += f0.y; a0z += f1.x; a0w += f1.y;
    }

    {   // self-loop
        uint2 r = __ldg(&H2[(size_t)node * 32 + lane]);
        float2 f0 = __half22float2(*(__half2*)&r.x);
        float2 f1 = __half22float2(*(__half2*)&r.y);
        a0x += f0.x; a0y += f0.y; a0z += f1.x; a0w += f1.y;
    }

    float dd = g_dis[node];
    float4 b = *(const float4*)&bias[lane * 4];
    float4 o;
    o.x = fmaxf(dd * (a0x + a1x) + b.x, 0.f);
    o.y = fmaxf(dd * (a0y + a1y) + b.y, 0.f);
    o.z = fmaxf(dd * (a0z + a1z) + b.z, 0.f);
    o.w = fmaxf(dd * (a0w + a1w) + b.w, 0.f);
    return o;
}

__global__ void k_agg_f32(const __half* __restrict__ H16, const float* __restrict__ bias,
                          float* __restrict__ out, int n) {
    int warp = (blockIdx.x * blockDim.x + threadIdx.x) >> 5;
    int lane = threadIdx.x & 31;
    if (warp >= n) return;
    float4 o = agg_core(H16, bias, warp, lane);
    ((float4*)out)[(size_t)warp * 32 + lane] = o;
}

__global__ void k_agg_pool(const __half* __restrict__ H16, const float* __restrict__ bias,
                           const int* __restrict__ batch, int n) {
    int warp = (blockIdx.x * blockDim.x + threadIdx.x) >> 5;
    int lane = threadIdx.x & 31;
    if (warp >= n) return;
    float4 o = agg_core(H16, bias, warp, lane);
    int b = __ldg(&batch[warp]);
    red_add_v4(&g_pool[(size_t)b * 128 + lane * 4], o);
}

// ---- pooling setup -----------------------------------------------------------
__global__ void k_pool_zero() {
    int i = blockIdx.x * blockDim.x + threadIdx.x;
    if (i < N_GRAPHS * HID) g_pool[i] = 0.0f;
    if (i < N_GRAPHS) g_cnt[i] = 0.0f;
}

__global__ void k_cnt(const int* __restrict__ batch, int n) {
    int i = blockIdx.x * blockDim.x + threadIdx.x;
    if (i < n) atomicAdd(&g_cnt[batch[i]], 1.0f);
}

// ---- MLP head ------------------------------------------------------------------
__global__ void k_mlp(const float* __restrict__ Wl1, const float* __restrict__ bl1,
                      const float* __restrict__ Wl2, const float* __restrict__ bl2,
                      float* __restrict__ out) {
    __shared__ float gm[128];
    __shared__ float hid[64];
    int gi = blockIdx.x;
    int t = threadIdx.x;  // 64 threads
    float inv = 1.0f / fmaxf(g_cnt[gi], 1.0f);
    gm[t]      = g_pool[(size_t)gi * 128 + t] * inv;
    gm[t + 64] = g_pool[(size_t)gi * 128 + t + 64] * inv;
    __syncthreads();
    float s = bl1[t];
    #pragma unroll 8
    for (int k = 0; k < 128; k++) s += gm[k] * Wl1[k * 64 + t];
    hid[t] = fmaxf(s, 0.0f);
    __syncthreads();
    if (t < 5) {
        float o = bl2[t];
        #pragma unroll
        for (int k = 0; k < 64; k++) o += hid[k] * Wl2[k * 5 + t];
        out[gi * 5 + t] = 1.0f / (1.0f + expf(-o));
    }
}

// ---------------------------------------------------------------------------
extern "C" void kernel_launch(void* const* d_in, const int* in_sizes, int n_in,
                              void* d_out, int out_size) {
    const float* x    = (const float*)d_in[0];
    const int*   ei   = (const int*)d_in[1];
    const int*   batch= (const int*)d_in[2];
    const float* W1   = (const float*)d_in[3];
    const float* b1   = (const float*)d_in[4];
    const float* W2   = (const float*)d_in[5];
    const float* b2   = (const float*)d_in[6];
    const float* Wl1  = (const float*)d_in[7];
    const float* bl1  = (const float*)d_in[8];
    const float* Wl2  = (const float*)d_in[9];
    const float* bl2  = (const float*)d_in[10];
    float* out = (float*)d_out;

    const int N = in_sizes[2];          // 50000
    const int E = in_sizes[1] / 2;      // 1600000
    const int* src = ei;
    const int* dst = ei + E;

    __half* H16 = 0;
    float* B = 0;
    cudaGetSymbolAddress((void**)&H16, g_H16);
    cudaGetSymbolAddress((void**)&B, g_B);

    const int T = 256;
    const int nb_scan = (N + 1 + 255) / 256;

    // CSR build + dis
    k_zero_deg<<<(N + T - 1) / T, T>>>(N);
    k_edge_count<<<(E + T - 1) / T, T>>>(dst, E);
    k_block_sums<<<nb_scan, 256>>>(N);
    k_scan_partials<<<1, 256>>>(nb_scan);
    k_scan_final<<<nb_scan, 256>>>(N);
    k_fill_csr<<<(E + T - 1) / T, T>>>(src, dst, E);

    // layer 1: mma gemm(x,W1) -> H16 (dis-scaled fp16) ; aggregate -> B (fp32)
    k_gemm_mma<IN_DIM><<<(N + 127) / 128, 256>>>(x, W1, H16, N);
    k_agg_f32<<<(N * 32 + T - 1) / T, T>>>(H16, b1, B, N);

    // layer 2: mma gemm(B,W2) -> H16 ; aggregate fused with pooling
    k_gemm_mma<HID><<<(N + 127) / 128, 256>>>(B, W2, H16, N);
    k_pool_zero<<<(N_GRAPHS * HID + T - 1) / T, T>>>();
    k_cnt<<<(N + T - 1) / T, T>>>(batch, N);
    k_agg_pool<<<(N * 32 + T - 1) / T, T>>>(H16, b2, batch, N);

    // head
    k_mlp<<<N_GRAPHS, 64>>>(Wl1, bl1, Wl2, bl2, out);
}

// round 9
// speedup vs baseline: 1.7820x; 1.0089x over previous
#include <cuda_runtime.h>
#include <cuda_fp16.h>
#include <cstdint>
#include <math.h>

typedef unsigned int u32;

// ---------------------------------------------------------------------------
// GNNRegressor: 2x GCNConv(+relu) -> global_mean_pool -> Linear+relu -> Linear+sigmoid
// N=50000, E=1.6M, IN=384, HID=128, G=512, OUT=5
// - CSR build overlapped with GEMM1 (GEMM1 is dis-free: unscaled rows;
//   layer-1 aggregate applies dis[s] per edge)
// - single-pass decoupled-lookback scan
// - tensor-core fp16 MMA GEMMs (fp32 accum)
// - fp16 inter-layer rows; layer-2 aggregate fuses mean-pool RED
// ---------------------------------------------------------------------------

#define N_NODES 50000
#define N_GRAPHS 512
#define HID 128
#define IN_DIM 384
#define E_MAX 1600000
#define NB_MAX 256

__device__ __half g_H16[(size_t)N_NODES * HID];   // gemm output rows (fp16)
__device__ __half g_B16[(size_t)N_NODES * HID];   // layer-1 aggregate output (fp16)
__device__ float  g_dis[N_NODES];
__device__ int    g_deg[N_NODES];
__device__ int    g_row[N_NODES + 1];
__device__ int    g_cursor[N_NODES];
__device__ int    g_csr[E_MAX];
__device__ u32    g_flag[NB_MAX];                 // lookback scan state
__device__ float  g_pool[(size_t)N_GRAPHS * HID];
__device__ float  g_cnt[N_GRAPHS];

__device__ __forceinline__ void red_add_v4(float* addr, float4 v) {
    asm volatile("red.global.add.v4.f32 [%0], {%1,%2,%3,%4};"
                 :: "l"(addr), "f"(v.x), "f"(v.y), "f"(v.z), "f"(v.w)
                 : "memory");
}

__device__ __forceinline__ void ldsm_x4(u32& r0, u32& r1, u32& r2, u32& r3, u32 addr) {
    asm volatile("ldmatrix.sync.aligned.m8n8.x4.shared.b16 {%0,%1,%2,%3}, [%4];"
                 : "=r"(r0), "=r"(r1), "=r"(r2), "=r"(r3) : "r"(addr));
}

__device__ __forceinline__ void ldsm_x4_t(u32& r0, u32& r1, u32& r2, u32& r3, u32 addr) {
    asm volatile("ldmatrix.sync.aligned.m8n8.x4.trans.shared.b16 {%0,%1,%2,%3}, [%4];"
                 : "=r"(r0), "=r"(r1), "=r"(r2), "=r"(r3) : "r"(addr));
}

__device__ __forceinline__ void mma16816(float& c0, float& c1, float& c2, float& c3,
                                         u32 a0, u32 a1, u32 a2, u32 a3,
                                         u32 b0, u32 b1) {
    asm volatile("mma.sync.aligned.m16n8k16.row.col.f32.f16.f16.f32 "
                 "{%0,%1,%2,%3}, {%4,%5,%6,%7}, {%8,%9}, {%0,%1,%2,%3};"
                 : "+f"(c0), "+f"(c1), "+f"(c2), "+f"(c3)
                 : "r"(a0), "r"(a1), "r"(a2), "r"(a3), "r"(b0), "r"(b1));
}

__device__ __forceinline__ u32 smem_addr(const void* p) {
    return (u32)__cvta_generic_to_shared(p);
}

// ---- zero everything that must be reset per call -----------------------------
__global__ void k_zero_all(int n, int nb) {
    int i = blockIdx.x * blockDim.x + threadIdx.x;
    if (i < n) g_deg[i] = 0;
    if (i < nb) g_flag[i] = 0u;
    if (i < N_GRAPHS * HID) g_pool[i] = 0.0f;
    if (i < N_GRAPHS) g_cnt[i] = 0.0f;
}

// ---- degree count + batch histogram (fused) ----------------------------------
__global__ void k_count(const int* __restrict__ dst, const int* __restrict__ batch,
                        int E, int n) {
    int i = blockIdx.x * blockDim.x + threadIdx.x;
    if (i < E) atomicAdd(&g_deg[dst[i]], 1);
    if (i < n) atomicAdd(&g_cnt[batch[i]], 1.0f);
}

// ---- single-pass decoupled-lookback exclusive scan of deg --------------------
// also writes cursor copy and dis = rsqrt(deg+1)
__global__ void k_scan_lb(int n) {
    __shared__ int sh[256];
    const int b = blockIdx.x;
    const int t = threadIdx.x;
    const int i = b * 256 + t;
    int v = (i < n) ? g_deg[i] : 0;
    sh[t] = v;
    __syncthreads();
    #pragma unroll
    for (int off = 1; off < 256; off <<= 1) {
        int x = (t >= off) ? sh[t - off] : 0;
        __syncthreads();
        sh[t] += x;
        __syncthreads();
    }
    int incl = sh[t];
    int total = sh[255];
    __syncthreads();

    if (t == 0) atomicExch(&g_flag[b], ((u32)total) | 0x80000000u);

    u32 pre = 0;
    if (t < b) {
        u32 u;
        do { u = atomicAdd(&g_flag[t], 0u); } while (!(u & 0x80000000u));
        pre = u & 0x7fffffffu;
    }
    sh[t] = (int)pre;
    __syncthreads();
    #pragma unroll
    for (int off = 128; off > 0; off >>= 1) {
        if (t < off) sh[t] += sh[t + off];
        __syncthreads();
    }
    int excl = sh[0] + incl - v;
    if (i <= n) {
        g_row[i] = excl;
        if (i < n) {
            g_cursor[i] = excl;
            g_dis[i] = rsqrtf((float)(v + 1));
        }
    }
}

__global__ void k_fill_csr(const int* __restrict__ src, const int* __restrict__ dst, int E) {
    int e = blockIdx.x * blockDim.x + threadIdx.x;
    if (e < E) {
        int d = dst[e];
        int pos = atomicAdd(&g_cursor[d], 1);
        g_csr[pos] = src[e];
    }
}

// ---- A-tile staging (fp32 or fp16 input) -------------------------------------
__device__ __forceinline__ void stage_a(const float* __restrict__ A, __half* As,
                                        int row0, int k0, int M, int t, int KTOT) {
    const int AP = 40;
    #pragma unroll
    for (int i = 0; i < 4; i++) {
        int idx = t * 4 + i;
        int r = idx >> 3;
        int seg = idx & 7;
        int gr = row0 + r;
        float4 v = (gr < M) ? *(const float4*)&A[(size_t)gr * KTOT + k0 + seg * 4]
                            : make_float4(0.f, 0.f, 0.f, 0.f);
        __half2 h0 = __floats2half2_rn(v.x, v.y);
        __half2 h1 = __floats2half2_rn(v.z, v.w);
        *(__half2*)&As[r * AP + seg * 4]     = h0;
        *(__half2*)&As[r * AP + seg * 4 + 2] = h1;
    }
}

__device__ __forceinline__ void stage_a(const __half* __restrict__ A, __half* As,
                                        int row0, int k0, int M, int t, int KTOT) {
    const int AP = 40;
    #pragma unroll
    for (int i = 0; i < 2; i++) {
        int idx = t * 2 + i;
        int r = idx >> 2;
        int seg = idx & 3;
        int gr = row0 + r;
        uint4 v = make_uint4(0u, 0u, 0u, 0u);
        if (gr < M) v = *(const uint4*)&A[(size_t)gr * KTOT + k0 + seg * 8];
        *(uint4*)&As[r * AP + seg * 8] = v;
    }
}

// ---- tensor-core GEMM ---------------------------------------------------------
// SCALE=true:  C16[row] = half( dis[row] * (A[row,:] @ W) )   (requires g_dis ready)
// SCALE=false: C16[row] = half( A[row,:] @ W )                (dis-free; overlappable)
template <int KTOT, bool SCALE, typename TA>
__global__ __launch_bounds__(256, 2)
void k_gemm_mma(const TA* __restrict__ A, const float* __restrict__ W,
                __half* __restrict__ C16, int M) {
    const int BM = 128, BN = 128, BK = 32;
    const int AP = 40;
    const int BP = 136;
    __shared__ __half As[128 * 40];
    __shared__ __half Bs[32 * 136];

    const int t = threadIdx.x;
    const int lane = t & 31;
    const int warp = t >> 5;
    const int wm = warp & 3;
    const int wn = warp >> 2;
    const int row0 = blockIdx.x * BM;
    const int lr = lane & 15;
    const int lc = lane >> 4;

    float c[2][8][4];
    #pragma unroll
    for (int i = 0; i < 2; i++)
        #pragma unroll
        for (int j = 0; j < 8; j++)
            #pragma unroll
            for (int k = 0; k < 4; k++) c[i][j][k] = 0.f;

    for (int k0 = 0; k0 < KTOT; k0 += BK) {
        stage_a(A, As, row0, k0, M, t, KTOT);
        #pragma unroll
        for (int i = 0; i < 4; i++) {
            int idx = t * 4 + i;
            int r = idx >> 5;
            int seg = idx & 31;
            float4 v = *(const float4*)&W[(size_t)(k0 + r) * BN + seg * 4];
            __half2 h0 = __floats2half2_rn(v.x, v.y);
            __half2 h1 = __floats2half2_rn(v.z, v.w);
            *(__half2*)&Bs[r * BP + seg * 4]     = h0;
            *(__half2*)&Bs[r * BP + seg * 4 + 2] = h1;
        }
        __syncthreads();

        #pragma unroll
        for (int ki = 0; ki < 2; ki++) {
            u32 a0[4];
            u32 a1[4];
            {
                u32 ad0 = smem_addr(&As[(wm * 32 + lr) * AP + ki * 16 + lc * 8]);
                ldsm_x4(a0[0], a0[1], a0[2], a0[3], ad0);
                u32 ad1 = smem_addr(&As[(wm * 32 + 16 + lr) * AP + ki * 16 + lc * 8]);
                ldsm_x4(a1[0], a1[1], a1[2], a1[3], ad1);
            }
            u32 b[4][4];
            #pragma unroll
            for (int np = 0; np < 4; np++) {
                u32 ad = smem_addr(&Bs[(ki * 16 + lr) * BP + wn * 64 + np * 16 + lc * 8]);
                ldsm_x4_t(b[np][0], b[np][1], b[np][2], b[np][3], ad);
            }
            #pragma unroll
            for (int np = 0; np < 4; np++) {
                mma16816(c[0][np * 2][0], c[0][np * 2][1], c[0][np * 2][2], c[0][np * 2][3],
                         a0[0], a0[1], a0[2], a0[3], b[np][0], b[np][1]);
                mma16816(c[0][np * 2 + 1][0], c[0][np * 2 + 1][1], c[0][np * 2 + 1][2], c[0][np * 2 + 1][3],
                         a0[0], a0[1], a0[2], a0[3], b[np][2], b[np][3]);
                mma16816(c[1][np * 2][0], c[1][np * 2][1], c[1][np * 2][2], c[1][np * 2][3],
                         a1[0], a1[1], a1[2], a1[3], b[np][0], b[np][1]);
                mma16816(c[1][np * 2 + 1][0], c[1][np * 2 + 1][1], c[1][np * 2 + 1][2], c[1][np * 2 + 1][3],
                         a1[0], a1[1], a1[2], a1[3], b[np][2], b[np][3]);
            }
        }
        __syncthreads();
    }

    #pragma unroll
    for (int mi = 0; mi < 2; mi++) {
        int r_lo = row0 + wm * 32 + mi * 16 + (lane >> 2);
        int r_hi = r_lo + 8;
        float d_lo = 1.0f, d_hi = 1.0f;
        if (SCALE) {
            d_lo = (r_lo < M) ? g_dis[r_lo] : 0.f;
            d_hi = (r_hi < M) ? g_dis[r_hi] : 0.f;
        }
        #pragma unroll
        for (int ni = 0; ni < 8; ni++) {
            int col = wn * 64 + ni * 8 + (lane & 3) * 2;
            if (r_lo < M) {
                __half2 h = __floats2half2_rn(d_lo * c[mi][ni][0], d_lo * c[mi][ni][1]);
                *(__half2*)&C16[(size_t)r_lo * 128 + col] = h;
            }
            if (r_hi < M) {
                __half2 h = __floats2half2_rn(d_hi * c[mi][ni][2], d_hi * c[mi][ni][3]);
                *(__half2*)&C16[(size_t)r_hi * 128 + col] = h;
            }
        }
    }
}

// ---- aggregate core ------------------------------------------------------------
// PRESCALED=true : rows already carry dis[s]; weight = 1        (layer 2)
// PRESCALED=false: rows unscaled; weight = dis[s] per edge      (layer 1)
template <bool PRESCALED>
__device__ __forceinline__ float4 agg_core(const __half* __restrict__ H16,
                                           const float* __restrict__ bias,
                                           int node, int lane) {
    const uint2* __restrict__ H2 = (const uint2*)H16;
    int beg = g_row[node];
    int end = g_row[node + 1];
    float dd = g_dis[node];

    float ax[4], ay[4], az[4], aw[4];
    #pragma unroll
    for (int q = 0; q < 4; q++) { ax[q] = 0.f; ay[q] = 0.f; az[q] = 0.f; aw[q] = 0.f; }

    int j = beg;
    for (; j + 3 < end; j += 4) {
        int s0 = __ldg(&g_csr[j + 0]);
        int s1 = __ldg(&g_csr[j + 1]);
        int s2 = __ldg(&g_csr[j + 2]);
        int s3 = __ldg(&g_csr[j + 3]);
        float w0 = 1.f, w1 = 1.f, w2 = 1.f, w3 = 1.f;
        if (!PRESCALED) {
            w0 = __ldg(&g_dis[s0]);
            w1 = __ldg(&g_dis[s1]);
            w2 = __ldg(&g_dis[s2]);
            w3 = __ldg(&g_dis[s3]);
        }
        uint2 r0 = __ldg(&H2[(size_t)s0 * 32 + lane]);
        uint2 r1 = __ldg(&H2[(size_t)s1 * 32 + lane]);
        uint2 r2 = __ldg(&H2[(size_t)s2 * 32 + lane]);
        uint2 r3 = __ldg(&H2[(size_t)s3 * 32 + lane]);
        float2 f0a = __half22float2(*(__half2*)&r0.x), f0b = __half22float2(*(__half2*)&r0.y);
        float2 f1a = __half22float2(*(__half2*)&r1.x), f1b = __half22float2(*(__half2*)&r1.y);
        float2 f2a = __half22float2(*(__half2*)&r2.x), f2b = __half22float2(*(__half2*)&r2.y);
        float2 f3a = __half22float2(*(__half2*)&r3.x), f3b = __half22float2(*(__half2*)&r3.y);
        if (PRESCALED) {
            ax[0] += f0a.x; ay[0] += f0a.y; az[0] += f0b.x; aw[0] += f0b.y;
            ax[1] += f1a.x; ay[1] += f1a.y; az[1] += f1b.x; aw[1] += f1b.y;
            ax[2] += f2a.x; ay[2] += f2a.y; az[2] += f2b.x; aw[2] += f2b.y;
            ax[3] += f3a.x; ay[3] += f3a.y; az[3] += f3b.x; aw[3] += f3b.y;
        } else {
            ax[0] += w0 * f0a.x; ay[0] += w0 * f0a.y; az[0] += w0 * f0b.x; aw[0] += w0 * f0b.y;
            ax[1] += w1 * f1a.x; ay[1] += w1 * f1a.y; az[1] += w1 * f1b.x; aw[1] += w1 * f1b.y;
            ax[2] += w2 * f2a.x; ay[2] += w2 * f2a.y; az[2] += w2 * f2b.x; aw[2] += w2 * f2b.y;
            ax[3] += w3 * f3a.x; ay[3] += w3 * f3a.y; az[3] += w3 * f3b.x; aw[3] += w3 * f3b.y;
        }
    }
    for (; j < end; j++) {
        int s = __ldg(&g_csr[j]);
        float w = PRESCALED ? 1.f : __ldg(&g_dis[s]);
        uint2 r = __ldg(&H2[(size_t)s * 32 + lane]);
        float2 fa = __half22float2(*(__half2*)&r.x);
        float2 fb = __half22float2(*(__half2*)&r.y);
        ax[0] += w * fa.x; ay[0] += w * fa.y; az[0] += w * fb.x; aw[0] += w * fb.y;
    }
    {   // self-loop
        float w = PRESCALED ? 1.f : dd;
        uint2 r = __ldg(&H2[(size_t)node * 32 + lane]);
        float2 fa = __half22float2(*(__half2*)&r.x);
        float2 fb = __half22float2(*(__half2*)&r.y);
        ax[1] += w * fa.x; ay[1] += w * fa.y; az[1] += w * fb.x; aw[1] += w * fb.y;
    }

    float4 b = *(const float4*)&bias[lane * 4];
    float4 o;
    o.x = fmaxf(dd * ((ax[0] + ax[1]) + (ax[2] + ax[3])) + b.x, 0.f);
    o.y = fmaxf(dd * ((ay[0] + ay[1]) + (ay[2] + ay[3])) + b.y, 0.f);
    o.z = fmaxf(dd * ((az[0] + az[1]) + (az[2] + az[3])) + b.z, 0.f);
    o.w = fmaxf(dd * ((aw[0] + aw[1]) + (aw[2] + aw[3])) + b.w, 0.f);
    return o;
}

// layer-1 aggregate: unscaled input rows, per-edge dis; writes fp16 rows
__global__ void k_agg_f16(const __half* __restrict__ H16, const float* __restrict__ bias,
                          __half* __restrict__ out16, int n) {
    int warp = (blockIdx.x * blockDim.x + threadIdx.x) >> 5;
    int lane = threadIdx.x & 31;
    if (warp >= n) return;
    float4 o = agg_core<false>(H16, bias, warp, lane);
    __half2 ha = __floats2half2_rn(o.x, o.y);
    __half2 hb = __floats2half2_rn(o.z, o.w);
    uint2 pack;
    pack.x = *(u32*)&ha;
    pack.y = *(u32*)&hb;
    ((uint2*)out16)[(size_t)warp * 32 + lane] = pack;
}

// layer-2 aggregate (prescaled rows) fused with mean-pool accumulation
__global__ void k_agg_pool(const __half* __restrict__ H16, const float* __restrict__ bias,
                           const int* __restrict__ batch, int n) {
    int warp = (blockIdx.x * blockDim.x + threadIdx.x) >> 5;
    int lane = threadIdx.x & 31;
    if (warp >= n) return;
    float4 o = agg_core<true>(H16, bias, warp, lane);
    int b = __ldg(&batch[warp]);
    red_add_v4(&g_pool[(size_t)b * 128 + lane * 4], o);
}

// ---- MLP head ------------------------------------------------------------------
__global__ void k_mlp(const float* __restrict__ Wl1, const float* __restrict__ bl1,
                      const float* __restrict__ Wl2, const float* __restrict__ bl2,
                      float* __restrict__ out) {
    __shared__ float gm[128];
    __shared__ float hid[64];
    int gi = blockIdx.x;
    int t = threadIdx.x;  // 64 threads
    float inv = 1.0f / fmaxf(g_cnt[gi], 1.0f);
    gm[t]      = g_pool[(size_t)gi * 128 + t] * inv;
    gm[t + 64] = g_pool[(size_t)gi * 128 + t + 64] * inv;
    __syncthreads();
    float s = bl1[t];
    #pragma unroll 8
    for (int k = 0; k < 128; k++) s += gm[k] * Wl1[k * 64 + t];
    hid[t] = fmaxf(s, 0.0f);
    __syncthreads();
    if (t < 5) {
        float o = bl2[t];
        #pragma unroll
        for (int k = 0; k < 64; k++) o += hid[k] * Wl2[k * 5 + t];
        out[gi * 5 + t] = 1.0f / (1.0f + expf(-o));
    }
}

// ---------------------------------------------------------------------------
extern "C" void kernel_launch(void* const* d_in, const int* in_sizes, int n_in,
                              void* d_out, int out_size) {
    const float* x    = (const float*)d_in[0];
    const int*   ei   = (const int*)d_in[1];
    const int*   batch= (const int*)d_in[2];
    const float* W1   = (const float*)d_in[3];
    const float* b1   = (const float*)d_in[4];
    const float* W2   = (const float*)d_in[5];
    const float* b2   = (const float*)d_in[6];
    const float* Wl1  = (const float*)d_in[7];
    const float* bl1  = (const float*)d_in[8];
    const float* Wl2  = (const float*)d_in[9];
    const float* bl2  = (const float*)d_in[10];
    float* out = (float*)d_out;

    const int N = in_sizes[2];          // 50000
    const int E = in_sizes[1] / 2;      // 1600000
    const int* src = ei;
    const int* dst = ei + E;

    __half* H16 = 0;
    __half* B16 = 0;
    cudaGetSymbolAddress((void**)&H16, g_H16);
    cudaGetSymbolAddress((void**)&B16, g_B16);

    const int T = 256;
    const int nb = (N + 1 + 255) / 256;
    const int zeroN = N_GRAPHS * HID;

    // fork a side stream for the CSR build (independent of dis-free GEMM1)
    cudaStream_t s1;
    cudaStreamCreateWithFlags(&s1, cudaStreamNonBlocking);
    cudaEvent_t e0, e1;
    cudaEventCreateWithFlags(&e0, cudaEventDisableTiming);
    cudaEventCreateWithFlags(&e1, cudaEventDisableTiming);

    cudaEventRecord(e0, 0);
    cudaStreamWaitEvent(s1, e0, 0);

    // side stream: CSR build + counts + dis
    k_zero_all<<<(zeroN + T - 1) / T, T, 0, s1>>>(N, nb);
    k_count<<<(E + T - 1) / T, T, 0, s1>>>(dst, batch, E, N);
    k_scan_lb<<<nb, 256, 0, s1>>>(N);
    k_fill_csr<<<(E + T - 1) / T, T, 0, s1>>>(src, dst, E);
    cudaEventRecord(e1, s1);

    // main stream: GEMM1 (unscaled output; touches neither g_dis nor CSR)
    k_gemm_mma<IN_DIM, false, float><<<(N + 127) / 128, 256>>>(x, W1, H16, N);

    // join, then the dependent chain
    cudaStreamWaitEvent(0, e1, 0);
    k_agg_f16<<<(N * 32 + T - 1) / T, T>>>(H16, b1, B16, N);
    k_gemm_mma<HID, true, __half><<<(N + 127) / 128, 256>>>(B16, W2, H16, N);
    k_agg_pool<<<(N * 32 + T - 1) / T, T>>>(H16, b2, batch, N);
    k_mlp<<<N_GRAPHS, 64>>>(Wl1, bl1, Wl2, bl2, out);

    // cleanup (skip while a capture is active)
    cudaStreamCaptureStatus st = cudaStreamCaptureStatusNone;
    cudaStreamIsCapturing(s1, &st);
    if (st == cudaStreamCaptureStatusNone) {
        cudaEventDestroy(e0);
        cudaEventDestroy(e1);
        cudaStreamDestroy(s1);
    }
}

// round 10
// speedup vs baseline: 1.8933x; 1.0624x over previous
#include <cuda_runtime.h>
#include <cuda_fp16.h>
#include <cstdint>
#include <math.h>

typedef unsigned int u32;

// ---------------------------------------------------------------------------
// GNNRegressor: 2x GCNConv(+relu) -> global_mean_pool -> Linear+relu -> Linear+sigmoid
// N=50000, E=1.6M, IN=384, HID=128, G=512, OUT=5
// - CSR build (4 edges/thread, deep atomic MLP) overlapped with dis-free GEMM1
// - single-pass decoupled-lookback scan
// - tensor-core fp16 MMA GEMMs (fp32 accum)
// - aggregates: 2 rows per LDG.128 (half-warp per row), shfl-combined
// ---------------------------------------------------------------------------

#define N_NODES 50000
#define N_GRAPHS 512
#define HID 128
#define IN_DIM 384
#define E_MAX 1600000
#define NB_MAX 256

__device__ __half g_H16[(size_t)N_NODES * HID];   // gemm output rows (fp16)
__device__ __half g_B16[(size_t)N_NODES * HID];   // layer-1 aggregate output (fp16)
__device__ float  g_dis[N_NODES];
__device__ int    g_deg[N_NODES];
__device__ int    g_row[N_NODES + 1];
__device__ int    g_cursor[N_NODES];
__device__ int    g_csr[E_MAX];
__device__ u32    g_flag[NB_MAX];
__device__ float  g_pool[(size_t)N_GRAPHS * HID];
__device__ float  g_cnt[N_GRAPHS];

__device__ __forceinline__ void red_add_v4(float* addr, float4 v) {
    asm volatile("red.global.add.v4.f32 [%0], {%1,%2,%3,%4};"
                 :: "l"(addr), "f"(v.x), "f"(v.y), "f"(v.z), "f"(v.w)
                 : "memory");
}

__device__ __forceinline__ void ldsm_x4(u32& r0, u32& r1, u32& r2, u32& r3, u32 addr) {
    asm volatile("ldmatrix.sync.aligned.m8n8.x4.shared.b16 {%0,%1,%2,%3}, [%4];"
                 : "=r"(r0), "=r"(r1), "=r"(r2), "=r"(r3) : "r"(addr));
}

__device__ __forceinline__ void ldsm_x4_t(u32& r0, u32& r1, u32& r2, u32& r3, u32 addr) {
    asm volatile("ldmatrix.sync.aligned.m8n8.x4.trans.shared.b16 {%0,%1,%2,%3}, [%4];"
                 : "=r"(r0), "=r"(r1), "=r"(r2), "=r"(r3) : "r"(addr));
}

__device__ __forceinline__ void mma16816(float& c0, float& c1, float& c2, float& c3,
                                         u32 a0, u32 a1, u32 a2, u32 a3,
                                         u32 b0, u32 b1) {
    asm volatile("mma.sync.aligned.m16n8k16.row.col.f32.f16.f16.f32 "
                 "{%0,%1,%2,%3}, {%4,%5,%6,%7}, {%8,%9}, {%0,%1,%2,%3};"
                 : "+f"(c0), "+f"(c1), "+f"(c2), "+f"(c3)
                 : "r"(a0), "r"(a1), "r"(a2), "r"(a3), "r"(b0), "r"(b1));
}

__device__ __forceinline__ u32 smem_addr(const void* p) {
    return (u32)__cvta_generic_to_shared(p);
}

// ---- zero everything that must be reset per call -----------------------------
__global__ void k_zero_all(int n, int nb) {
    int i = blockIdx.x * blockDim.x + threadIdx.x;
    if (i < n) g_deg[i] = 0;
    if (i < nb) g_flag[i] = 0u;
    if (i < N_GRAPHS * HID) g_pool[i] = 0.0f;
    if (i < N_GRAPHS) g_cnt[i] = 0.0f;
}

// ---- degree count + batch histogram: 4 edges per thread ----------------------
__global__ void k_count(const int* __restrict__ dst, const int* __restrict__ batch,
                        int E, int n) {
    int t = blockIdx.x * blockDim.x + threadIdx.x;
    int base = t * 4;
    #pragma unroll
    for (int i = 0; i < 4; i++) {
        int e = base + i;
        if (e < E) atomicAdd(&g_deg[__ldg(&dst[e])], 1);
    }
    if (t < n) atomicAdd(&g_cnt[__ldg(&batch[t])], 1.0f);
}

// ---- single-pass decoupled-lookback exclusive scan of deg --------------------
__global__ void k_scan_lb(int n) {
    __shared__ int sh[256];
    const int b = blockIdx.x;
    const int t = threadIdx.x;
    const int i = b * 256 + t;
    int v = (i < n) ? g_deg[i] : 0;
    sh[t] = v;
    __syncthreads();
    #pragma unroll
    for (int off = 1; off < 256; off <<= 1) {
        int x = (t >= off) ? sh[t - off] : 0;
        __syncthreads();
        sh[t] += x;
        __syncthreads();
    }
    int incl = sh[t];
    int total = sh[255];
    __syncthreads();

    if (t == 0) atomicExch(&g_flag[b], ((u32)total) | 0x80000000u);

    u32 pre = 0;
    if (t < b) {
        u32 u;
        do { u = atomicAdd(&g_flag[t], 0u); } while (!(u & 0x80000000u));
        pre = u & 0x7fffffffu;
    }
    sh[t] = (int)pre;
    __syncthreads();
    #pragma unroll
    for (int off = 128; off > 0; off >>= 1) {
        if (t < off) sh[t] += sh[t + off];
        __syncthreads();
    }
    int excl = sh[0] + incl - v;
    if (i <= n) {
        g_row[i] = excl;
        if (i < n) {
            g_cursor[i] = excl;
            g_dis[i] = rsqrtf((float)(v + 1));
        }
    }
}

// ---- CSR fill: 4 edges per thread (deep atomic MLP) --------------------------
__global__ void k_fill_csr(const int* __restrict__ src, const int* __restrict__ dst, int E) {
    int base = (blockIdx.x * blockDim.x + threadIdx.x) * 4;
    #pragma unroll
    for (int i = 0; i < 4; i++) {
        int e = base + i;
        if (e < E) {
            int d = __ldg(&dst[e]);
            int pos = atomicAdd(&g_cursor[d], 1);
            g_csr[pos] = __ldg(&src[e]);
        }
    }
}

// ---- A-tile staging (fp32 or fp16 input) -------------------------------------
__device__ __forceinline__ void stage_a(const float* __restrict__ A, __half* As,
                                        int row0, int k0, int M, int t, int KTOT) {
    const int AP = 40;
    #pragma unroll
    for (int i = 0; i < 4; i++) {
        int idx = t * 4 + i;
        int r = idx >> 3;
        int seg = idx & 7;
        int gr = row0 + r;
        float4 v = (gr < M) ? *(const float4*)&A[(size_t)gr * KTOT + k0 + seg * 4]
                            : make_float4(0.f, 0.f, 0.f, 0.f);
        __half2 h0 = __floats2half2_rn(v.x, v.y);
        __half2 h1 = __floats2half2_rn(v.z, v.w);
        *(__half2*)&As[r * AP + seg * 4]     = h0;
        *(__half2*)&As[r * AP + seg * 4 + 2] = h1;
    }
}

__device__ __forceinline__ void stage_a(const __half* __restrict__ A, __half* As,
                                        int row0, int k0, int M, int t, int KTOT) {
    const int AP = 40;
    #pragma unroll
    for (int i = 0; i < 2; i++) {
        int idx = t * 2 + i;
        int r = idx >> 2;
        int seg = idx & 3;
        int gr = row0 + r;
        uint4 v = make_uint4(0u, 0u, 0u, 0u);
        if (gr < M) v = *(const uint4*)&A[(size_t)gr * KTOT + k0 + seg * 8];
        *(uint4*)&As[r * AP + seg * 8] = v;
    }
}

// ---- tensor-core GEMM ---------------------------------------------------------
template <int KTOT, bool SCALE, typename TA>
__global__ __launch_bounds__(256, 2)
void k_gemm_mma(const TA* __restrict__ A, const float* __restrict__ W,
                __half* __restrict__ C16, int M) {
    const int BM = 128, BN = 128, BK = 32;
    const int AP = 40;
    const int BP = 136;
    __shared__ __half As[128 * 40];
    __shared__ __half Bs[32 * 136];

    const int t = threadIdx.x;
    const int lane = t & 31;
    const int warp = t >> 5;
    const int wm = warp & 3;
    const int wn = warp >> 2;
    const int row0 = blockIdx.x * BM;
    const int lr = lane & 15;
    const int lc = lane >> 4;

    float c[2][8][4];
    #pragma unroll
    for (int i = 0; i < 2; i++)
        #pragma unroll
        for (int j = 0; j < 8; j++)
            #pragma unroll
            for (int k = 0; k < 4; k++) c[i][j][k] = 0.f;

    for (int k0 = 0; k0 < KTOT; k0 += BK) {
        stage_a(A, As, row0, k0, M, t, KTOT);
        #pragma unroll
        for (int i = 0; i < 4; i++) {
            int idx = t * 4 + i;
            int r = idx >> 5;
            int seg = idx & 31;
            float4 v = *(const float4*)&W[(size_t)(k0 + r) * BN + seg * 4];
            __half2 h0 = __floats2half2_rn(v.x, v.y);
            __half2 h1 = __floats2half2_rn(v.z, v.w);
            *(__half2*)&Bs[r * BP + seg * 4]     = h0;
            *(__half2*)&Bs[r * BP + seg * 4 + 2] = h1;
        }
        __syncthreads();

        #pragma unroll
        for (int ki = 0; ki < 2; ki++) {
            u32 a0[4];
            u32 a1[4];
            {
                u32 ad0 = smem_addr(&As[(wm * 32 + lr) * AP + ki * 16 + lc * 8]);
                ldsm_x4(a0[0], a0[1], a0[2], a0[3], ad0);
                u32 ad1 = smem_addr(&As[(wm * 32 + 16 + lr) * AP + ki * 16 + lc * 8]);
                ldsm_x4(a1[0], a1[1], a1[2], a1[3], ad1);
            }
            u32 b[4][4];
            #pragma unroll
            for (int np = 0; np < 4; np++) {
                u32 ad = smem_addr(&Bs[(ki * 16 + lr) * BP + wn * 64 + np * 16 + lc * 8]);
                ldsm_x4_t(b[np][0], b[np][1], b[np][2], b[np][3], ad);
            }
            #pragma unroll
            for (int np = 0; np < 4; np++) {
                mma16816(c[0][np * 2][0], c[0][np * 2][1], c[0][np * 2][2], c[0][np * 2][3],
                         a0[0], a0[1], a0[2], a0[3], b[np][0], b[np][1]);
                mma16816(c[0][np * 2 + 1][0], c[0][np * 2 + 1][1], c[0][np * 2 + 1][2], c[0][np * 2 + 1][3],
                         a0[0], a0[1], a0[2], a0[3], b[np][2], b[np][3]);
                mma16816(c[1][np * 2][0], c[1][np * 2][1], c[1][np * 2][2], c[1][np * 2][3],
                         a1[0], a1[1], a1[2], a1[3], b[np][0], b[np][1]);
                mma16816(c[1][np * 2 + 1][0], c[1][np * 2 + 1][1], c[1][np * 2 + 1][2], c[1][np * 2 + 1][3],
                         a1[0], a1[1], a1[2], a1[3], b[np][2], b[np][3]);
            }
        }
        __syncthreads();
    }

    #pragma unroll
    for (int mi = 0; mi < 2; mi++) {
        int r_lo = row0 + wm * 32 + mi * 16 + (lane >> 2);
        int r_hi = r_lo + 8;
        float d_lo = 1.0f, d_hi = 1.0f;
        if (SCALE) {
            d_lo = (r_lo < M) ? g_dis[r_lo] : 0.f;
            d_hi = (r_hi < M) ? g_dis[r_hi] : 0.f;
        }
        #pragma unroll
        for (int ni = 0; ni < 8; ni++) {
            int col = wn * 64 + ni * 8 + (lane & 3) * 2;
            if (r_lo < M) {
                __half2 h = __floats2half2_rn(d_lo * c[mi][ni][0], d_lo * c[mi][ni][1]);
                *(__half2*)&C16[(size_t)r_lo * 128 + col] = h;
            }
            if (r_hi < M) {
                __half2 h = __floats2half2_rn(d_hi * c[mi][ni][2], d_hi * c[mi][ni][3]);
                *(__half2*)&C16[(size_t)r_hi * 128 + col] = h;
            }
        }
    }
}

// ---- aggregate core: half-warp per row, LDG.128 per lane ---------------------
// Lane l: group g = l>>4 handles the even(g=0)/odd(g=1) edge of each pair;
// sub-lane k = l&15 covers feature cols [8k, 8k+8) as one uint4 (8 halves).
// After the loop, shfl_xor(16) combines the two groups.
// PRESCALED=true : rows already carry dis[s] (layer 2)
// PRESCALED=false: weight dis[s] per edge (layer 1)
template <bool PRESCALED>
__device__ __forceinline__ void agg_core(const __half* __restrict__ H16,
                                         int node, int lane, float dd, float* f) {
    const uint4* __restrict__ H4 = (const uint4*)H16;  // 16 uint4 per row
    const int g = lane >> 4;
    const int k = lane & 15;
    int beg = g_row[node];
    int end = g_row[node + 1];

    #pragma unroll
    for (int i = 0; i < 8; i++) f[i] = 0.f;
    float f2[8];
    #pragma unroll
    for (int i = 0; i < 8; i++) f2[i] = 0.f;

    int j = beg;
    // 4 edges (2 pairs) per iteration
    for (; j + 3 < end; j += 4) {
        int s0 = __ldg(&g_csr[j + 0]);
        int s1 = __ldg(&g_csr[j + 1]);
        int s2 = __ldg(&g_csr[j + 2]);
        int s3 = __ldg(&g_csr[j + 3]);
        int sa = g ? s1 : s0;
        int sb = g ? s3 : s2;
        float wa = PRESCALED ? 1.f : __ldg(&g_dis[sa]);
        float wb = PRESCALED ? 1.f : __ldg(&g_dis[sb]);
        uint4 ra = __ldg(&H4[(size_t)sa * 16 + k]);
        uint4 rb = __ldg(&H4[(size_t)sb * 16 + k]);
        const u32* pa = (const u32*)&ra;
        const u32* pb = (const u32*)&rb;
        #pragma unroll
        for (int q = 0; q < 4; q++) {
            float2 va = __half22float2(*(__half2*)&pa[q]);
            float2 vb = __half22float2(*(__half2*)&pb[q]);
            if (PRESCALED) {
                f[q * 2]     += va.x;
                f[q * 2 + 1] += va.y;
                f2[q * 2]     += vb.x;
                f2[q * 2 + 1] += vb.y;
            } else {
                f[q * 2]     += wa * va.x;
                f[q * 2 + 1] += wa * va.y;
                f2[q * 2]     += wb * vb.x;
                f2[q * 2 + 1] += wb * vb.y;
            }
        }
    }
    // one pair
    for (; j + 1 < end; j += 2) {
        int s0 = __ldg(&g_csr[j]);
        int s1 = __ldg(&g_csr[j + 1]);
        int sa = g ? s1 : s0;
        float wa = PRESCALED ? 1.f : __ldg(&g_dis[sa]);
        uint4 ra = __ldg(&H4[(size_t)sa * 16 + k]);
        const u32* pa = (const u32*)&ra;
        #pragma unroll
        for (int q = 0; q < 4; q++) {
            float2 va = __half22float2(*(__half2*)&pa[q]);
            f[q * 2]     += PRESCALED ? va.x : wa * va.x;
            f[q * 2 + 1] += PRESCALED ? va.y : wa * va.y;
        }
    }
    // leftover edge + self-loop folded into one pair slot
    {
        int rem = end - j;      // 0 or 1
        int sa;
        float wa;
        bool active = true;
        if (rem) {
            // g=0 -> leftover edge, g=1 -> self loop
            int s0 = __ldg(&g_csr[j]);
            sa = g ? node : s0;
            wa = PRESCALED ? 1.f : (g ? dd : __ldg(&g_dis[sa]));
        } else {
            sa = node;
            wa = PRESCALED ? 1.f : dd;
            active = (g == 0);
        }
        if (active) {
            uint4 ra = __ldg(&H4[(size_t)sa * 16 + k]);
            const u32* pa = (const u32*)&ra;
            #pragma unroll
            for (int q = 0; q < 4; q++) {
                float2 va = __half22float2(*(__half2*)&pa[q]);
                f[q * 2]     += PRESCALED ? va.x : wa * va.x;
                f[q * 2 + 1] += PRESCALED ? va.y : wa * va.y;
            }
        }
    }

    // combine local pair-halves, then cross-group
    #pragma unroll
    for (int i = 0; i < 8; i++) f[i] += f2[i];
    #pragma unroll
    for (int i = 0; i < 8; i++) f[i] += __shfl_xor_sync(0xffffffffu, f[i], 16);
}

// layer-1 aggregate: writes fp16 rows (relu(dd*sum + bias))
__global__ void k_agg_f16(const __half* __restrict__ H16, const float* __restrict__ bias,
                          __half* __restrict__ out16, int n) {
    int node = (blockIdx.x * blockDim.x + threadIdx.x) >> 5;
    int lane = threadIdx.x & 31;
    if (node >= n) return;
    float dd = g_dis[node];
    float f[8];
    agg_core<false>(H16, node, lane, dd, f);
    int k = lane & 15;
    if ((lane >> 4) == 0) {
        float4 b0 = *(const float4*)&bias[k * 8];
        float4 b1 = *(const float4*)&bias[k * 8 + 4];
        __half2 h0 = __floats2half2_rn(fmaxf(dd * f[0] + b0.x, 0.f), fmaxf(dd * f[1] + b0.y, 0.f));
        __half2 h1 = __floats2half2_rn(fmaxf(dd * f[2] + b0.z, 0.f), fmaxf(dd * f[3] + b0.w, 0.f));
        __half2 h2 = __floats2half2_rn(fmaxf(dd * f[4] + b1.x, 0.f), fmaxf(dd * f[5] + b1.y, 0.f));
        __half2 h3 = __floats2half2_rn(fmaxf(dd * f[6] + b1.z, 0.f), fmaxf(dd * f[7] + b1.w, 0.f));
        uint4 pack;
        pack.x = *(u32*)&h0;
        pack.y = *(u32*)&h1;
        pack.z = *(u32*)&h2;
        pack.w = *(u32*)&h3;
        ((uint4*)out16)[(size_t)node * 16 + k] = pack;
    }
}

// layer-2 aggregate (prescaled rows) fused with mean-pool RED
__global__ void k_agg_pool(const __half* __restrict__ H16, const float* __restrict__ bias,
                           const int* __restrict__ batch, int n) {
    int node = (blockIdx.x * blockDim.x + threadIdx.x) >> 5;
    int lane = threadIdx.x & 31;
    if (node >= n) return;
    float dd = g_dis[node];
    float f[8];
    agg_core<true>(H16, node, lane, dd, f);
    int k = lane & 15;
    int g = lane >> 4;
    int b = __ldg(&batch[node]);
    // group 0 REDs cols [8k,8k+4), group 1 REDs [8k+4,8k+8)
    const float* bi = &bias[k * 8 + g * 4];
    float4 v;
    v.x = fmaxf(dd * f[g * 4 + 0] + bi[0], 0.f);
    v.y = fmaxf(dd * f[g * 4 + 1] + bi[1], 0.f);
    v.z = fmaxf(dd * f[g * 4 + 2] + bi[2], 0.f);
    v.w = fmaxf(dd * f[g * 4 + 3] + bi[3], 0.f);
    red_add_v4(&g_pool[(size_t)b * 128 + k * 8 + g * 4], v);
}

// ---- MLP head ------------------------------------------------------------------
__global__ void k_mlp(const float* __restrict__ Wl1, const float* __restrict__ bl1,
                      const float* __restrict__ Wl2, const float* __restrict__ bl2,
                      float* __restrict__ out) {
    __shared__ float gm[128];
    __shared__ float hid[64];
    int gi = blockIdx.x;
    int t = threadIdx.x;  // 64 threads
    float inv = 1.0f / fmaxf(g_cnt[gi], 1.0f);
    gm[t]      = g_pool[(size_t)gi * 128 + t] * inv;
    gm[t + 64] = g_pool[(size_t)gi * 128 + t + 64] * inv;
    __syncthreads();
    float s = bl1[t];
    #pragma unroll 8
    for (int k = 0; k < 128; k++) s += gm[k] * Wl1[k * 64 + t];
    hid[t] = fmaxf(s, 0.0f);
    __syncthreads();
    if (t < 5) {
        float o = bl2[t];
        #pragma unroll
        for (int k = 0; k < 64; k++) o += hid[k] * Wl2[k * 5 + t];
        out[gi * 5 + t] = 1.0f / (1.0f + expf(-o));
    }
}

// ---------------------------------------------------------------------------
extern "C" void kernel_launch(void* const* d_in, const int* in_sizes, int n_in,
                              void* d_out, int out_size) {
    const float* x    = (const float*)d_in[0];
    const int*   ei   = (const int*)d_in[1];
    const int*   batch= (const int*)d_in[2];
    const float* W1   = (const float*)d_in[3];
    const float* b1   = (const float*)d_in[4];
    const float* W2   = (const float*)d_in[5];
    const float* b2   = (const float*)d_in[6];
    const float* Wl1  = (const float*)d_in[7];
    const float* bl1  = (const float*)d_in[8];
    const float* Wl2  = (const float*)d_in[9];
    const float* bl2  = (const float*)d_in[10];
    float* out = (float*)d_out;

    const int N = in_sizes[2];          // 50000
    const int E = in_sizes[1] / 2;      // 1600000
    const int* src = ei;
    const int* dst = ei + E;

    __half* H16 = 0;
    __half* B16 = 0;
    cudaGetSymbolAddress((void**)&H16, g_H16);
    cudaGetSymbolAddress((void**)&B16, g_B16);

    const int T = 256;
    const int nb = (N + 1 + 255) / 256;
    const int zeroN = N_GRAPHS * HID;
    const int e4 = (E + 3) / 4;                 // threads for 4-edge kernels

    // fork a side stream for the CSR build (independent of dis-free GEMM1)
    cudaStream_t s1;
    cudaStreamCreateWithFlags(&s1, cudaStreamNonBlocking);
    cudaEvent_t e0, e1;
    cudaEventCreateWithFlags(&e0, cudaEventDisableTiming);
    cudaEventCreateWithFlags(&e1, cudaEventDisableTiming);

    cudaEventRecord(e0, 0);
    cudaStreamWaitEvent(s1, e0, 0);

    // side stream: CSR build + counts + dis
    k_zero_all<<<(zeroN + T - 1) / T, T, 0, s1>>>(N, nb);
    k_count<<<(e4 + T - 1) / T, T, 0, s1>>>(dst, batch, E, N);
    k_scan_lb<<<nb, 256, 0, s1>>>(N);
    k_fill_csr<<<(e4 + T - 1) / T, T, 0, s1>>>(src, dst, E);
    cudaEventRecord(e1, s1);

    // main stream: GEMM1 (unscaled output; independent of g_dis / CSR)
    k_gemm_mma<IN_DIM, false, float><<<(N + 127) / 128, 256>>>(x, W1, H16, N);

    // join, then the dependent chain
    cudaStreamWaitEvent(0, e1, 0);
    k_agg_f16<<<(N * 32 + T - 1) / T, T>>>(H16, b1, B16, N);
    k_gemm_mma<HID, true, __half><<<(N + 127) / 128, 256>>>(B16, W2, H16, N);
    k_agg_pool<<<(N * 32 + T - 1) / T, T>>>(H16, b2, batch, N);
    k_mlp<<<N_GRAPHS, 64>>>(Wl1, bl1, Wl2, bl2, out);

    // cleanup (skip while a capture is active)
    cudaStreamCaptureStatus st = cudaStreamCaptureStatusNone;
    cudaStreamIsCapturing(s1, &st);
    if (st == cudaStreamCaptureStatusNone) {
        cudaEventDestroy(e0);
        cudaEventDestroy(e1);
        cudaStreamDestroy(s1);
    }
}